// round 2
// baseline (speedup 1.0000x reference)
#include <cuda_runtime.h>
#include <math.h>
#include <stdint.h>

#define L 512
#define B 32
#define D 256
#define H 256
#define G 768           // 3*H
#define LB (L*B)        // 16384

// ---------------- scratch (static device globals; no allocation) ----------------
__device__ float g_tp[LB*H];            // tanh(Wp  v)     [i,b,h]
__device__ float g_u [LB*H];            // V * tp          [i,b,h]
__device__ float g_tq[LB*H];            // tanh(Wp_ v)     [l,b,h]
__device__ float g_w [LB*H];            // V * tq          [l,b,h]
__device__ float g_S [LB*L];            // scores/softmax  [i,b,l]
__device__ float g_c [LB*D];            // context         [i,b,d]
__device__ float g_gi[LB*G];            // W_ih c + b_ih   [i,b,3H]

// ---------------- helpers ----------------
__device__ __forceinline__ float frcp_approx(float x) {
    float r;
    asm("rcp.approx.f32 %0, %1;" : "=f"(r) : "f"(x));
    return r;
}

__device__ __forceinline__ uint32_t smem_u32(const void* p) {
    uint32_t a;
    asm("{ .reg .u64 t; cvta.to.shared.u64 t, %1; cvt.u32.u64 %0, t; }" : "=r"(a) : "l"(p));
    return a;
}

__device__ __forceinline__ void st_shared_cluster_f32(uint32_t laddr, uint32_t rank, float v) {
    asm volatile(
        "{ .reg .b32 ra; mapa.shared::cluster.u32 ra, %0, %1; st.shared::cluster.f32 [ra], %2; }"
        :: "r"(laddr), "r"(rank), "f"(v) : "memory");
}

__device__ __forceinline__ void cluster_sync_all() {
    // arrive has release, wait has acquire semantics -> orders the DSMEM stores
    asm volatile("barrier.cluster.arrive.aligned;" ::: "memory");
    asm volatile("barrier.cluster.wait.aligned;" ::: "memory");
}

// ---------------- 1) projection GEMM + tanh epilogue ----------------
// T[n,h] = tanh( sum_d X[n,d] * W[h,d] ),  Uo[n,h] = Vv[b,h]*T[n,h],  b = n%32
__global__ __launch_bounds__(256) void proj_kernel(
    const float* __restrict__ X, const float* __restrict__ W,
    const float* __restrict__ Vv, float* __restrict__ T, float* __restrict__ Uo)
{
    __shared__ float Xs[64][33];
    __shared__ float Ws[64][33];
    int n0 = blockIdx.x * 64, h0 = blockIdx.y * 64;
    int t = threadIdx.x;
    int ti = t >> 4, tl = t & 15;
    float acc[4][4] = {};

    for (int k0 = 0; k0 < 256; k0 += 32) {
        #pragma unroll
        for (int it = 0; it < 8; ++it) {
            int idx = t + it * 256;
            int r = idx >> 5, kk = idx & 31;
            Xs[r][kk] = X[(n0 + r) * 256 + k0 + kk];
            Ws[r][kk] = W[(h0 + r) * 256 + k0 + kk];
        }
        __syncthreads();
        #pragma unroll
        for (int kk = 0; kk < 32; ++kk) {
            float a[4], bb[4];
            #pragma unroll
            for (int i = 0; i < 4; ++i) a[i] = Xs[ti * 4 + i][kk];
            #pragma unroll
            for (int j = 0; j < 4; ++j) bb[j] = Ws[tl + 16 * j][kk];
            #pragma unroll
            for (int i = 0; i < 4; ++i)
                #pragma unroll
                for (int j = 0; j < 4; ++j)
                    acc[i][j] = fmaf(a[i], bb[j], acc[i][j]);
        }
        __syncthreads();
    }
    #pragma unroll
    for (int i = 0; i < 4; ++i) {
        int n = n0 + ti * 4 + i;
        int b = n & 31;
        #pragma unroll
        for (int j = 0; j < 4; ++j) {
            int h = h0 + tl + 16 * j;
            float tv = tanhf(acc[i][j]);
            T [n * 256 + h] = tv;
            Uo[n * 256 + h] = Vv[b * 256 + h] * tv;
        }
    }
}

// ---------------- 2) scores: S[i,b,l] = sum_h (u_i + w_l) / (1 + tp_i*tq_l) ----------------
// tanh(a+b) = (tanh a + tanh b) / (1 + tanh a * tanh b); u = V*tp, w = V*tq.
__global__ __launch_bounds__(256) void scores_kernel()
{
    __shared__ float TPs[64][33], Us[64][33], TQs[64][33], WWs[64][33];
    int b = blockIdx.z;
    int l0 = blockIdx.x * 64, i0 = blockIdx.y * 64;
    int t = threadIdx.x;
    int ti = t >> 4, tl = t & 15;
    float acc[4][4] = {};

    for (int h0 = 0; h0 < 256; h0 += 32) {
        #pragma unroll
        for (int it = 0; it < 8; ++it) {
            int idx = t + it * 256;
            int r = idx >> 5, kk = idx & 31;
            int io = ((i0 + r) * 32 + b) * 256 + h0 + kk;
            int lo = ((l0 + r) * 32 + b) * 256 + h0 + kk;
            TPs[r][kk] = g_tp[io];
            Us [r][kk] = g_u [io];
            TQs[r][kk] = g_tq[lo];
            WWs[r][kk] = g_w [lo];
        }
        __syncthreads();
        #pragma unroll
        for (int kk = 0; kk < 32; ++kk) {
            float tp[4], uu[4], tq[4], ww[4];
            #pragma unroll
            for (int i = 0; i < 4; ++i) { tp[i] = TPs[ti * 4 + i][kk]; uu[i] = Us[ti * 4 + i][kk]; }
            #pragma unroll
            for (int j = 0; j < 4; ++j) { tq[j] = TQs[tl + 16 * j][kk]; ww[j] = WWs[tl + 16 * j][kk]; }
            #pragma unroll
            for (int i = 0; i < 4; ++i)
                #pragma unroll
                for (int j = 0; j < 4; ++j) {
                    float den = fmaf(tp[i], tq[j], 1.0f);
                    float rr  = frcp_approx(den);
                    acc[i][j] = fmaf(uu[i] + ww[j], rr, acc[i][j]);
                }
        }
        __syncthreads();
    }
    #pragma unroll
    for (int i = 0; i < 4; ++i)
        #pragma unroll
        for (int j = 0; j < 4; ++j)
            g_S[((i0 + ti * 4 + i) * 32 + b) * 512 + l0 + tl + 16 * j] = acc[i][j];
}

// ---------------- 3) softmax over l, in place on g_S ----------------
__global__ __launch_bounds__(128) void softmax_kernel()
{
    int row = blockIdx.x;
    float* p = g_S + (size_t)row * 512;
    int t = threadIdx.x;
    float4 x = reinterpret_cast<float4*>(p)[t];
    float m = fmaxf(fmaxf(x.x, x.y), fmaxf(x.z, x.w));
    #pragma unroll
    for (int o = 16; o; o >>= 1) m = fmaxf(m, __shfl_xor_sync(0xffffffffu, m, o));
    __shared__ float redm[4];
    if ((t & 31) == 0) redm[t >> 5] = m;
    __syncthreads();
    m = fmaxf(fmaxf(redm[0], redm[1]), fmaxf(redm[2], redm[3]));
    float e0 = expf(x.x - m), e1 = expf(x.y - m), e2 = expf(x.z - m), e3 = expf(x.w - m);
    float s = e0 + e1 + e2 + e3;
    #pragma unroll
    for (int o = 16; o; o >>= 1) s += __shfl_xor_sync(0xffffffffu, s, o);
    __shared__ float reds[4];
    if ((t & 31) == 0) reds[t >> 5] = s;
    __syncthreads();
    s = reds[0] + reds[1] + reds[2] + reds[3];
    float inv = 1.0f / s;
    reinterpret_cast<float4*>(p)[t] = make_float4(e0 * inv, e1 * inv, e2 * inv, e3 * inv);
}

// ---------------- 4) context: c[i,b,d] = sum_l A[i,b,l]*v[l,b,d] ----------------
__global__ __launch_bounds__(256) void context_kernel(const float* __restrict__ v)
{
    __shared__ float As[64][33];   // [i_loc][l_chunk]
    __shared__ float Vs[32][65];   // [l_loc][d]
    int b = blockIdx.z;
    int d0 = blockIdx.x * 64, i0 = blockIdx.y * 64;
    int t = threadIdx.x;
    int ti = t >> 4, tl = t & 15;
    float acc[4][4] = {};

    for (int l0 = 0; l0 < 512; l0 += 32) {
        #pragma unroll
        for (int it = 0; it < 8; ++it) {
            int idx = t + it * 256;
            int r = idx >> 5, ll = idx & 31;
            As[r][ll] = g_S[((i0 + r) * 32 + b) * 512 + l0 + ll];
        }
        #pragma unroll
        for (int it = 0; it < 8; ++it) {
            int idx = t + it * 256;
            int ll = idx >> 6, dd = idx & 63;
            Vs[ll][dd] = v[((l0 + ll) * 32 + b) * 256 + d0 + dd];
        }
        __syncthreads();
        #pragma unroll
        for (int ll = 0; ll < 32; ++ll) {
            float a[4], bb[4];
            #pragma unroll
            for (int i = 0; i < 4; ++i) a[i] = As[ti * 4 + i][ll];
            #pragma unroll
            for (int j = 0; j < 4; ++j) bb[j] = Vs[ll][tl + 16 * j];
            #pragma unroll
            for (int i = 0; i < 4; ++i)
                #pragma unroll
                for (int j = 0; j < 4; ++j)
                    acc[i][j] = fmaf(a[i], bb[j], acc[i][j]);
        }
        __syncthreads();
    }
    #pragma unroll
    for (int i = 0; i < 4; ++i)
        #pragma unroll
        for (int j = 0; j < 4; ++j)
            g_c[((i0 + ti * 4 + i) * 32 + b) * 256 + d0 + tl + 16 * j] = acc[i][j];
}

// ---------------- 5) gi = c @ W_ih^T + b_ih ----------------
__global__ __launch_bounds__(256) void gi_kernel(const float* __restrict__ W_ih,
                                                 const float* __restrict__ b_ih)
{
    __shared__ float Xs[64][33];
    __shared__ float Ws[64][33];
    int j0 = blockIdx.x * 64, n0 = blockIdx.y * 64;
    int t = threadIdx.x;
    int ti = t >> 4, tl = t & 15;
    float acc[4][4] = {};

    for (int k0 = 0; k0 < 256; k0 += 32) {
        #pragma unroll
        for (int it = 0; it < 8; ++it) {
            int idx = t + it * 256;
            int r = idx >> 5, kk = idx & 31;
            Xs[r][kk] = g_c[(n0 + r) * 256 + k0 + kk];
            Ws[r][kk] = W_ih[(j0 + r) * 256 + k0 + kk];
        }
        __syncthreads();
        #pragma unroll
        for (int kk = 0; kk < 32; ++kk) {
            float a[4], bb[4];
            #pragma unroll
            for (int i = 0; i < 4; ++i) a[i] = Xs[ti * 4 + i][kk];
            #pragma unroll
            for (int j = 0; j < 4; ++j) bb[j] = Ws[tl + 16 * j][kk];
            #pragma unroll
            for (int i = 0; i < 4; ++i)
                #pragma unroll
                for (int j = 0; j < 4; ++j)
                    acc[i][j] = fmaf(a[i], bb[j], acc[i][j]);
        }
        __syncthreads();
    }
    #pragma unroll
    for (int i = 0; i < 4; ++i) {
        int n = n0 + ti * 4 + i;
        #pragma unroll
        for (int j = 0; j < 4; ++j) {
            int jj = j0 + tl + 16 * j;
            g_gi[n * 768 + jj] = acc[i][j] + b_ih[jj];
        }
    }
}

// ---------------- 6) GRU recurrence: cluster of 8 CTAs per batch ----------------
// CTA rank k owns rows {k*32..k*32+31} of each of the 3 gates (96 rows of W_hh),
// stored transposed in SMEM: Wt[d*96 + j].
// Each step: local 96-row GEMV on h, gates for h_new[32k..32k+32), DSMEM
// broadcast of those 32 values to all 8 CTAs (double-buffered h), 1 cluster sync.
#define GRU_SMEM_FLOATS (96*256 + 2*256 + 96 + 96)
#define GRU_SMEM_BYTES  (GRU_SMEM_FLOATS * 4)

__global__ void __cluster_dims__(8, 1, 1) __launch_bounds__(128, 1)
gru_kernel(const float* __restrict__ h0in, const float* __restrict__ W_hh,
           const float* __restrict__ b_hh, float* __restrict__ hs)
{
    extern __shared__ float sm[];
    float* Wt    = sm;                    // 96*256, transposed slice
    float* hbuf  = sm + 96 * 256;         // 2*256 double buffer (16B aligned)
    float* gh_s  = hbuf + 512;            // 96
    float* bhh_s = gh_s + 96;             // 96

    int tid  = threadIdx.x;               // 128 threads
    int b    = blockIdx.x >> 3;           // batch
    int rank = blockIdx.x & 7;            // cluster rank

    // Load transposed W_hh slice: local row j -> global row gate*256 + rank*32 + (j%32)
    for (int idx = tid; idx < 96 * 256; idx += 128) {
        int j = idx >> 8;
        int d = idx & 255;
        int gate = j >> 5, jj = j & 31;
        int grow = gate * 256 + rank * 32 + jj;
        Wt[d * 96 + j] = W_hh[grow * 256 + d];
    }
    if (tid < 96) {
        int gate = tid >> 5, jj = tid & 31;
        bhh_s[tid] = b_hh[gate * 256 + rank * 32 + jj];
    }
    for (int d = tid; d < 256; d += 128) hbuf[d] = h0in[b * 256 + d];
    __syncthreads();
    cluster_sync_all();   // everyone initialized before DSMEM traffic starts

    int p = 0;
    for (int i = 0; i < 512; ++i) {
        if (tid < 96) {
            const float* hcur = hbuf + p * 256;
            float a0 = 0.f, a1 = 0.f, a2 = 0.f, a3 = 0.f;
            #pragma unroll 4
            for (int d4 = 0; d4 < 64; ++d4) {
                float4 h4 = reinterpret_cast<const float4*>(hcur)[d4];
                int base = d4 * 4 * 96 + tid;
                a0 = fmaf(Wt[base       ], h4.x, a0);
                a1 = fmaf(Wt[base +  96 ], h4.y, a1);
                a2 = fmaf(Wt[base + 192 ], h4.z, a2);
                a3 = fmaf(Wt[base + 288 ], h4.w, a3);
            }
            gh_s[tid] = (a0 + a1) + (a2 + a3) + bhh_s[tid];
        }
        __syncthreads();
        if (tid < 32) {
            int jg = rank * 32 + tid;     // global h index
            const float* gi = g_gi + ((size_t)i * 32 + b) * 768;
            float ghr = gh_s[tid], ghz = gh_s[tid + 32], ghn = gh_s[tid + 64];
            float ir = gi[jg], iz = gi[256 + jg], inn = gi[512 + jg];
            float r = 1.0f / (1.0f + expf(-(ir + ghr)));
            float z = 1.0f / (1.0f + expf(-(iz + ghz)));
            float n = tanhf(inn + r * ghn);
            float hold = hbuf[p * 256 + jg];
            float hnew = (1.0f - z) * n + z * hold;
            // broadcast into every cluster CTA's next h buffer
            uint32_t laddr = smem_u32(&hbuf[(1 - p) * 256 + jg]);
            #pragma unroll
            for (uint32_t rr = 0; rr < 8; ++rr) st_shared_cluster_f32(laddr, rr, hnew);
            hs[((size_t)i * 32 + b) * 256 + jg] = hnew;
        }
        cluster_sync_all();   // orders DSMEM stores; releases hbuf[p] for reuse
        p ^= 1;
    }
}

// ---------------- launch ----------------
extern "C" void kernel_launch(void* const* d_in, const int* in_sizes, int n_in,
                              void* d_out, int out_size)
{
    const float* v    = (const float*)d_in[0];
    const float* h0   = (const float*)d_in[1];
    const float* Vv   = (const float*)d_in[2];
    const float* Wp   = (const float*)d_in[3];
    const float* Wp_  = (const float*)d_in[4];
    const float* W_ih = (const float*)d_in[5];
    const float* W_hh = (const float*)d_in[6];
    const float* b_ih = (const float*)d_in[7];
    const float* b_hh = (const float*)d_in[8];
    float* hs = (float*)d_out;
    (void)in_sizes; (void)n_in; (void)out_size;

    // Real device addresses of the __device__ scratch symbols (array decay of a
    // __device__ symbol in host code is NOT a valid device pointer).
    float *d_tp = 0, *d_u = 0, *d_tq = 0, *d_w = 0;
    cudaGetSymbolAddress((void**)&d_tp, g_tp);
    cudaGetSymbolAddress((void**)&d_u,  g_u);
    cudaGetSymbolAddress((void**)&d_tq, g_tq);
    cudaGetSymbolAddress((void**)&d_w,  g_w);

    dim3 blk(256);
    proj_kernel<<<dim3(LB / 64, H / 64), blk>>>(v, Wp,  Vv, d_tp, d_u);
    proj_kernel<<<dim3(LB / 64, H / 64), blk>>>(v, Wp_, Vv, d_tq, d_w);
    scores_kernel<<<dim3(L / 64, L / 64, B), blk>>>();
    softmax_kernel<<<LB, 128>>>();
    context_kernel<<<dim3(D / 64, L / 64, B), blk>>>(v);
    gi_kernel<<<dim3(G / 64, LB / 64), blk>>>(W_ih, b_ih);

    cudaFuncSetAttribute(gru_kernel, cudaFuncAttributeMaxDynamicSharedMemorySize, GRU_SMEM_BYTES);
    gru_kernel<<<B * 8, 128, GRU_SMEM_BYTES>>>(h0, W_hh, b_hh, hs);
}